// round 11
// baseline (speedup 1.0000x reference)
#include <cuda_runtime.h>
#include <cuda_bf16.h>
#include <cstdint>
#include <cstddef>

// ---------------------------------------------------------------------------
// Problem constants
// ---------------------------------------------------------------------------
constexpr int Bc = 256;
constexpr int Tc = 128;
constexpr int Dc = 1024;
constexpr int Hc = 1024;
constexpr int Gc = 3 * Hc;        // 3072
constexpr int M1 = Bc * Tc;       // 32768
constexpr int Kc = 1024;

// ---------------------------------------------------------------------------
// Device scratch (static: no cudaMalloc allowed)
// ---------------------------------------------------------------------------
__device__ float         g_gi[(size_t)M1 * Gc];          // 402 MB: x @ W_ih^T + b_ih
__device__ float         g_gh[(size_t)Bc * Gc];          // per-step h @ W_hh^T + b_hh
__device__ float         g_hf[Bc * Hc];                  // masked h (fp32) entering current step
__device__ __nv_bfloat16 g_hh_hi[Bc * Hc];
__device__ __nv_bfloat16 g_hh_lo[Bc * Hc];
__device__ __nv_bfloat16 g_x_hi[(size_t)M1 * Dc];
__device__ __nv_bfloat16 g_x_lo[(size_t)M1 * Dc];
__device__ __nv_bfloat16 g_wih_hi[(size_t)Gc * Dc];
__device__ __nv_bfloat16 g_wih_lo[(size_t)Gc * Dc];
__device__ __nv_bfloat16 g_whh_hi[(size_t)Gc * Hc];
__device__ __nv_bfloat16 g_whh_lo[(size_t)Gc * Hc];
__device__ float         g_mask[M1];                     // (~is_init) as float
__device__ int           g_mode;                         // 0=int32, 1=bool8, 2=float32

// ---------------------------------------------------------------------------
// PTX helpers
// ---------------------------------------------------------------------------
__device__ __forceinline__ void cp16(uint32_t s, const void* g) {
    asm volatile("cp.async.cg.shared.global [%0], [%1], 16;" :: "r"(s), "l"(g));
}
__device__ __forceinline__ void ldsm4(uint32_t& r0, uint32_t& r1, uint32_t& r2, uint32_t& r3, uint32_t a) {
    asm volatile("ldmatrix.sync.aligned.m8n8.x4.shared.b16 {%0,%1,%2,%3}, [%4];"
                 : "=r"(r0), "=r"(r1), "=r"(r2), "=r"(r3) : "r"(a));
}
__device__ __forceinline__ void mma16816(float* c, const uint32_t* a, const uint32_t* b) {
    asm volatile("mma.sync.aligned.m16n8k16.row.col.f32.bf16.bf16.f32 "
                 "{%0,%1,%2,%3}, {%4,%5,%6,%7}, {%8,%9}, {%0,%1,%2,%3};"
                 : "+f"(c[0]), "+f"(c[1]), "+f"(c[2]), "+f"(c[3])
                 : "r"(a[0]), "r"(a[1]), "r"(a[2]), "r"(a[3]), "r"(b[0]), "r"(b[1]));
}

// ---------------------------------------------------------------------------
// Split-bf16 GEMM:  C[M,N] = (Ahi+Alo)[M,K] * (Bhi+Blo)[N,K]^T + bias[N]
// 3 MMA passes: hi*hi + hi*lo + lo*hi  (lo*lo dropped, ~2^-18 rel)
// A is [M,K] row-major (the mma "row" operand); B is [N,K] row-major, which
// IS the "col" layout (k-contiguous at fixed n) -> BOTH operands use plain
// (non-trans) ldmatrix. (R8 bug: .trans on B swapped k/n -> garbage.)
// ---------------------------------------------------------------------------
template<int BM, int BN, int WMS, int WNS>
__global__ void __launch_bounds__(WMS * WNS * 32)
gemm_split(const __nv_bfloat16* __restrict__ Ahi, const __nv_bfloat16* __restrict__ Alo,
           const __nv_bfloat16* __restrict__ Bhi, const __nv_bfloat16* __restrict__ Blo,
           const float* __restrict__ bias, float* __restrict__ C,
           int M, int N, int K)
{
    constexpr int NTHR  = WMS * WNS * 32;
    constexpr int WM    = BM / WMS;
    constexpr int WN    = BN / WNS;
    constexpr int MT    = WM / 16;
    constexpr int NT    = WN / 8;
    constexpr int LD    = 40;                 // 32 data bf16 + 8 pad (80B row -> conflict-free ldmatrix)
    constexpr int TA    = BM * LD;            // elems per A split tile
    constexpr int TB    = BN * LD;
    constexpr int STAGE = 2 * TA + 2 * TB;    // elems per stage (Ahi,Alo,Bhi,Blo)

    extern __shared__ __align__(16) __nv_bfloat16 smem[];

    const int tid  = threadIdx.x;
    const int lane = tid & 31;
    const int wid  = tid >> 5;
    const int wm   = wid / WNS;
    const int wn   = wid % WNS;
    const int tM   = blockIdx.y * BM;
    const int tN   = blockIdx.x * BN;
    const uint32_t sbase = (uint32_t)__cvta_generic_to_shared(smem);

    auto issue = [&](int kt, int st) {
        const int k0 = kt * 32;
        uint32_t aHi = sbase + (uint32_t)(st * STAGE) * 2u;
        uint32_t aLo = aHi + TA * 2;
        uint32_t bHi = aLo + TA * 2;
        uint32_t bLo = bHi + TB * 2;
        for (int c = tid; c < BM * 4; c += NTHR) {
            int r = c >> 2, q = c & 3;
            size_t go = (size_t)(tM + r) * K + k0 + q * 8;
            uint32_t so = (uint32_t)(r * LD + q * 8) * 2u;
            cp16(aHi + so, Ahi + go);
            cp16(aLo + so, Alo + go);
        }
        for (int c = tid; c < BN * 4; c += NTHR) {
            int r = c >> 2, q = c & 3;
            size_t go = (size_t)(tN + r) * K + k0 + q * 8;
            uint32_t so = (uint32_t)(r * LD + q * 8) * 2u;
            cp16(bHi + so, Bhi + go);
            cp16(bLo + so, Blo + go);
        }
        asm volatile("cp.async.commit_group;");
    };

    float acc[MT][NT][4];
#pragma unroll
    for (int i = 0; i < MT; i++)
#pragma unroll
        for (int j = 0; j < NT; j++)
#pragma unroll
            for (int k = 0; k < 4; k++) acc[i][j][k] = 0.f;

    const int NKT = K / 32;
    issue(0, 0);

    for (int kt = 0; kt < NKT; kt++) {
        const int st = kt & 1;
        if (kt + 1 < NKT) {
            issue(kt + 1, st ^ 1);
            asm volatile("cp.async.wait_group 1;");
        } else {
            asm volatile("cp.async.wait_group 0;");
        }
        __syncthreads();

        uint32_t aHi = sbase + (uint32_t)(st * STAGE) * 2u;
        uint32_t aLo = aHi + TA * 2;
        uint32_t bHi = aLo + TA * 2;
        uint32_t bLo = bHi + TB * 2;

#pragma unroll
        for (int kk = 0; kk < 32; kk += 16) {
            uint32_t ah[MT][4], al[MT][4];
#pragma unroll
            for (int mt = 0; mt < MT; mt++) {
                // x4 matrices m0..m3 = {rows 0-7 k0-7, rows 8-15 k0-7,
                //                        rows 0-7 k8-15, rows 8-15 k8-15}
                int row = wm * WM + mt * 16 + (lane & 7) + ((lane >> 3) & 1) * 8;
                int col = kk + (lane >> 4) * 8;
                uint32_t off = (uint32_t)(row * LD + col) * 2u;
                ldsm4(ah[mt][0], ah[mt][1], ah[mt][2], ah[mt][3], aHi + off);
                ldsm4(al[mt][0], al[mt][1], al[mt][2], al[mt][3], aLo + off);
            }
            uint32_t bh[NT][2], bl[NT][2];
#pragma unroll
            for (int p = 0; p < NT / 2; p++) {
                // Non-trans x4 over 16 n-rows x 16 k:
                //   lanes  0-7  -> n0-7,  k0-7   = b0 of n-tile 0
                //   lanes  8-15 -> n0-7,  k8-15  = b1 of n-tile 0
                //   lanes 16-23 -> n8-15, k0-7   = b0 of n-tile 1
                //   lanes 24-31 -> n8-15, k8-15  = b1 of n-tile 1
                int nrow = wn * WN + p * 16 + ((lane >> 4) << 3) + (lane & 7);
                int kcol = kk + ((lane >> 3) & 1) * 8;
                uint32_t off = (uint32_t)(nrow * LD + kcol) * 2u;
                ldsm4(bh[2 * p][0], bh[2 * p][1], bh[2 * p + 1][0], bh[2 * p + 1][1], bHi + off);
                ldsm4(bl[2 * p][0], bl[2 * p][1], bl[2 * p + 1][0], bl[2 * p + 1][1], bLo + off);
            }
#pragma unroll
            for (int mt = 0; mt < MT; mt++)
#pragma unroll
                for (int nt = 0; nt < NT; nt++) {
                    mma16816(acc[mt][nt], ah[mt], bh[nt]);   // hi*hi
                    mma16816(acc[mt][nt], ah[mt], bl[nt]);   // hi*lo
                    mma16816(acc[mt][nt], al[mt], bh[nt]);   // lo*hi
                }
        }
        __syncthreads();
    }

    // Epilogue: add bias, store fp32 (float2 per fragment row)
#pragma unroll
    for (int mt = 0; mt < MT; mt++) {
#pragma unroll
        for (int nt = 0; nt < NT; nt++) {
            int gr = tM + wm * WM + mt * 16 + (lane >> 2);
            int gc = tN + wn * WN + nt * 8 + (lane & 3) * 2;
            float b0 = bias[gc], b1 = bias[gc + 1];
            float2 v0 = make_float2(acc[mt][nt][0] + b0, acc[mt][nt][1] + b1);
            float2 v1 = make_float2(acc[mt][nt][2] + b0, acc[mt][nt][3] + b1);
            *reinterpret_cast<float2*>(C + (size_t)gr * N + gc)       = v0;
            *reinterpret_cast<float2*>(C + (size_t)(gr + 8) * N + gc) = v1;
        }
    }
}

// ---------------------------------------------------------------------------
// Mask dtype detection: is_init may arrive as bool8 / int32 / float32.
// Scan first 32768 bytes (safe under all layouts). int32 0/1 -> bytes at
// offset%4!=0 are all zero. float 1.0f -> byte 0x3F at offset%4==3.
// ---------------------------------------------------------------------------
__global__ void detect_kernel(const unsigned char* __restrict__ p) {
    __shared__ int nz_off, f3;
    if (threadIdx.x == 0) { nz_off = 0; f3 = 0; }
    __syncthreads();
    int local_nz = 0, local_f3 = 0;
    for (int i = threadIdx.x; i < M1; i += blockDim.x) {
        unsigned char c = p[i];
        if ((i & 3) != 0 && c) local_nz = 1;
        if ((i & 3) == 3 && c == 0x3F) local_f3 = 1;
    }
    if (local_nz) atomicOr(&nz_off, 1);
    if (local_f3) atomicOr(&f3, 1);
    __syncthreads();
    if (threadIdx.x == 0) g_mode = (!nz_off) ? 0 : (f3 ? 2 : 1);
}

__global__ void mask_kernel(const void* __restrict__ p) {
    int i = blockIdx.x * blockDim.x + threadIdx.x;
    if (i >= M1) return;
    int mode = g_mode;
    int v;
    if (mode == 0)      v = (((const int*)p)[i] != 0);
    else if (mode == 1) v = (((const unsigned char*)p)[i] != 0);
    else                v = (((const float*)p)[i] != 0.f);
    g_mask[i] = v ? 0.f : 1.f;   // mask = ~is_init
}

// ---------------------------------------------------------------------------
// fp32 -> (bf16 hi, bf16 lo) split
// ---------------------------------------------------------------------------
__global__ void split_f32(const float* __restrict__ src,
                          __nv_bfloat16* __restrict__ hi, __nv_bfloat16* __restrict__ lo,
                          long n) {
    long stride = (long)gridDim.x * blockDim.x;
    for (long i = (long)blockIdx.x * blockDim.x + threadIdx.x; i < n; i += stride) {
        float v = src[i];
        __nv_bfloat16 h = __float2bfloat16(v);
        hi[i] = h;
        lo[i] = __float2bfloat16(v - __bfloat162float(h));
    }
}

// ---------------------------------------------------------------------------
// h0 = hx * mask[:,0], split to bf16 hi/lo
// ---------------------------------------------------------------------------
__global__ void init_h_kernel(const float* __restrict__ hx) {
    int idx = blockIdx.x * blockDim.x + threadIdx.x;
    if (idx >= Bc * Hc) return;
    int b = idx >> 10;
    float v = hx[idx] * g_mask[(size_t)b * Tc + 0];
    g_hf[idx] = v;
    __nv_bfloat16 h = __float2bfloat16(v);
    g_hh_hi[idx] = h;
    g_hh_lo[idx] = __float2bfloat16(v - __bfloat162float(h));
}

// ---------------------------------------------------------------------------
// GRU pointwise step: gates, h update, write Hseq, prep next-step masked h.
// ---------------------------------------------------------------------------
__global__ void gru_pointwise(float* __restrict__ Hseq, int t) {
    int idx = blockIdx.x * blockDim.x + threadIdx.x;
    if (idx >= Bc * Hc) return;
    int b = idx >> 10, j = idx & 1023;

    size_t gib = (size_t)(b * Tc + t) * Gc + j;
    float ir  = g_gi[gib];
    float iz  = g_gi[gib + 1024];
    float inn = g_gi[gib + 2048];

    size_t ghb = (size_t)b * Gc + j;
    float hr = g_gh[ghb];
    float hz = g_gh[ghb + 1024];
    float hn = g_gh[ghb + 2048];

    float h = g_hf[idx];   // already masked for step t
    float r = 1.f / (1.f + expf(-(ir + hr)));
    float z = 1.f / (1.f + expf(-(iz + hz)));
    float n = tanhf(inn + r * hn);
    float hnew = (1.f - z) * n + z * h;

    Hseq[(size_t)(b * Tc + t) * Hc + j] = hnew;

    float m  = (t + 1 < Tc) ? g_mask[(size_t)b * Tc + t + 1] : 0.f;
    float hm = hnew * m;
    g_hf[idx] = hm;
    __nv_bfloat16 hhh = __float2bfloat16(hm);
    g_hh_hi[idx] = hhh;
    g_hh_lo[idx] = __float2bfloat16(hm - __bfloat162float(hhh));
}

// ---------------------------------------------------------------------------
// LayerNorm(Hseq) * g + b + x * sigmoid(res_gate) -> Y.  One block per row.
// ---------------------------------------------------------------------------
__global__ void ln_kernel(const float* __restrict__ Hseq, const float* __restrict__ x,
                          const float* __restrict__ gg, const float* __restrict__ bb,
                          const float* __restrict__ res_gate, float* __restrict__ Y) {
    int m = blockIdx.x;
    const float* row = Hseq + (size_t)m * Hc;
    int tid = threadIdx.x;           // 128 threads, 8 elems each
    int lane = tid & 31, wid = tid >> 5;

    float v[8];
    float s = 0.f, s2 = 0.f;
#pragma unroll
    for (int i = 0; i < 8; i++) {
        float t = row[tid + i * 128];
        v[i] = t; s += t; s2 += t * t;
    }
#pragma unroll
    for (int o = 16; o; o >>= 1) {
        s  += __shfl_xor_sync(0xffffffffu, s, o);
        s2 += __shfl_xor_sync(0xffffffffu, s2, o);
    }
    __shared__ float red[8];
    if (lane == 0) { red[wid] = s; red[4 + wid] = s2; }
    __syncthreads();
    float ts  = red[0] + red[1] + red[2] + red[3];
    float ts2 = red[4] + red[5] + red[6] + red[7];
    float mu  = ts * (1.f / Hc);
    float var = ts2 * (1.f / Hc) - mu * mu;
    float rs  = rsqrtf(var + 1e-5f);

#pragma unroll
    for (int i = 0; i < 8; i++) {
        int j = tid + i * 128;
        float res = 1.f / (1.f + expf(-res_gate[j]));
        Y[(size_t)m * Hc + j] = (v[i] - mu) * rs * gg[j] + bb[j]
                              + x[(size_t)m * Hc + j] * res;
    }
}

// ---------------------------------------------------------------------------
// Launch
// ---------------------------------------------------------------------------
extern "C" void kernel_launch(void* const* d_in, const int* in_sizes, int n_in,
                              void* d_out, int out_size) {
    (void)in_sizes; (void)n_in; (void)out_size;
    const float* x        = (const float*)d_in[0];
    const float* hx       = (const float*)d_in[1];
    const void*  is_init  = d_in[2];
    const float* W_ih     = (const float*)d_in[3];
    const float* W_hh     = (const float*)d_in[4];
    const float* b_ih     = (const float*)d_in[5];
    const float* b_hh     = (const float*)d_in[6];
    const float* ln_g     = (const float*)d_in[7];
    const float* ln_b     = (const float*)d_in[8];
    const float* res_gate = (const float*)d_in[9];

    float* Y    = (float*)d_out;
    float* Hseq = Y + (size_t)M1 * Hc;   // tuple order: (Y, Hseq)

    void *p_gi, *p_gh, *p_xhi, *p_xlo, *p_wihhi, *p_wihlo, *p_whhhi, *p_whhlo, *p_hhhi, *p_hhlo;
    cudaGetSymbolAddress(&p_gi,    g_gi);
    cudaGetSymbolAddress(&p_gh,    g_gh);
    cudaGetSymbolAddress(&p_xhi,   g_x_hi);
    cudaGetSymbolAddress(&p_xlo,   g_x_lo);
    cudaGetSymbolAddress(&p_wihhi, g_wih_hi);
    cudaGetSymbolAddress(&p_wihlo, g_wih_lo);
    cudaGetSymbolAddress(&p_whhhi, g_whh_hi);
    cudaGetSymbolAddress(&p_whhlo, g_whh_lo);
    cudaGetSymbolAddress(&p_hhhi,  g_hh_hi);
    cudaGetSymbolAddress(&p_hhlo,  g_hh_lo);

    // dynamic smem: big GEMM 80 KB, step GEMM 40 KB
    constexpr int SMEM_BIG  = 2 * (2 * 128 * 40 + 2 * 128 * 40) * 2;   // 81920
    constexpr int SMEM_STEP = 2 * (2 * 64 * 40 + 2 * 64 * 40) * 2;     // 40960
    cudaFuncSetAttribute(gemm_split<128, 128, 4, 2>,
                         cudaFuncAttributeMaxDynamicSharedMemorySize, SMEM_BIG);
    cudaFuncSetAttribute(gemm_split<64, 64, 2, 2>,
                         cudaFuncAttributeMaxDynamicSharedMemorySize, SMEM_STEP);

    // 1) mask
    detect_kernel<<<1, 256>>>((const unsigned char*)is_init);
    mask_kernel<<<(M1 + 255) / 256, 256>>>(is_init);

    // 2) splits
    split_f32<<<8192, 256>>>(x,    (__nv_bfloat16*)p_xhi,   (__nv_bfloat16*)p_xlo,   (long)M1 * Dc);
    split_f32<<<2048, 256>>>(W_ih, (__nv_bfloat16*)p_wihhi, (__nv_bfloat16*)p_wihlo, (long)Gc * Dc);
    split_f32<<<2048, 256>>>(W_hh, (__nv_bfloat16*)p_whhhi, (__nv_bfloat16*)p_whhlo, (long)Gc * Hc);

    // 3) gi = x @ W_ih^T + b_ih   [32768 x 3072]
    gemm_split<128, 128, 4, 2><<<dim3(Gc / 128, M1 / 128), 256, SMEM_BIG>>>(
        (const __nv_bfloat16*)p_xhi,   (const __nv_bfloat16*)p_xlo,
        (const __nv_bfloat16*)p_wihhi, (const __nv_bfloat16*)p_wihlo,
        b_ih, (float*)p_gi, M1, Gc, Kc);

    // 4) h0
    init_h_kernel<<<(Bc * Hc + 255) / 256, 256>>>(hx);

    // 5) recurrence: 128 x (GEMM + pointwise)
    for (int t = 0; t < Tc; t++) {
        gemm_split<64, 64, 2, 2><<<dim3(Gc / 64, Bc / 64), 128, SMEM_STEP>>>(
            (const __nv_bfloat16*)p_hhhi,  (const __nv_bfloat16*)p_hhlo,
            (const __nv_bfloat16*)p_whhhi, (const __nv_bfloat16*)p_whhlo,
            b_hh, (float*)p_gh, Bc, Gc, Kc);
        gru_pointwise<<<(Bc * Hc + 255) / 256, 256>>>(Hseq, t);
    }

    // 6) Y = LN(Hseq)*g + b + x*sigmoid(res_gate)
    ln_kernel<<<M1, 128>>>(Hseq, x, ln_g, ln_b, res_gate, Y);
}